// round 13
// baseline (speedup 1.0000x reference)
#include <cuda_runtime.h>
#include <cuda_fp16.h>
#include <cstdint>

// ---------------- problem constants ----------------
#define T_DIM 8192
#define D_DIM 4096

// ---------------- scratch (static device globals; no allocation) ----------------
static __device__ __half g_w1[(size_t)D_DIM * D_DIM];
static __device__ __half g_w2[(size_t)D_DIM * D_DIM];
static __device__ __half g_x [(size_t)T_DIM * D_DIM];
static __device__ __half g_h [(size_t)T_DIM * D_DIM];

__constant__ float c_lut[16] = {0.f, 0.5f, 1.f, 1.5f, 2.f, 3.f, 4.f, 6.f,
                                -0.f, -0.5f, -1.f, -1.5f, -2.f, -3.f, -4.f, -6.f};

// ---------------- PTX helpers ----------------
__device__ __forceinline__ void cp16(void* s, const void* g) {
    uint32_t sa = (uint32_t)__cvta_generic_to_shared(s);
    asm volatile("cp.async.cg.shared.global [%0], [%1], 16;\n" :: "r"(sa), "l"(g));
}
__device__ __forceinline__ void cp_commit() { asm volatile("cp.async.commit_group;\n"); }
__device__ __forceinline__ void cp_wait1()  { asm volatile("cp.async.wait_group 1;\n"); }

__device__ __forceinline__ void ldsm4(uint32_t* r, const void* p) {
    uint32_t a = (uint32_t)__cvta_generic_to_shared(p);
    asm volatile("ldmatrix.sync.aligned.m8n8.x4.shared.b16 {%0,%1,%2,%3}, [%4];\n"
                 : "=r"(r[0]), "=r"(r[1]), "=r"(r[2]), "=r"(r[3]) : "r"(a));
}
__device__ __forceinline__ void mma16816(float* c, const uint32_t* a, const uint32_t* b) {
    asm volatile("mma.sync.aligned.m16n8k16.row.col.f32.f16.f16.f32 "
                 "{%0,%1,%2,%3}, {%4,%5,%6,%7}, {%8,%9}, {%0,%1,%2,%3};\n"
                 : "+f"(c[0]), "+f"(c[1]), "+f"(c[2]), "+f"(c[3])
                 : "r"(a[0]), "r"(a[1]), "r"(a[2]), "r"(a[3]), "r"(b[0]), "r"(b[1]));
}

// ---------------- prologue kernels (unchanged) ----------------
__global__ void cvt_kernel(const float* __restrict__ x,
                           __half* __restrict__ out, int total4) {
    int i = blockIdx.x * blockDim.x + threadIdx.x;
    if (i >= total4) return;
    float4 v = reinterpret_cast<const float4*>(x)[i];
    reinterpret_cast<__half2*>(out)[2 * i + 0] = __floats2half2_rn(v.x, v.y);
    reinterpret_cast<__half2*>(out)[2 * i + 1] = __floats2half2_rn(v.z, v.w);
}

// Dequantize MXFP4 -> fp16 (exact: <=2 mantissa bits, magnitudes 2^-7..12)
__global__ void dequant_kernel(const int* __restrict__ codes,
                               const float* __restrict__ scales,
                               __half* __restrict__ out, int total4) {
    int i = blockIdx.x * blockDim.x + threadIdx.x;
    if (i >= total4) return;
    int4 c = reinterpret_cast<const int4*>(codes)[i];
    int base = i * 4;
    int row = base >> 12;            // / D_DIM
    int kk  = base & (D_DIM - 1);
    float s = __ldg(&scales[row * (D_DIM >> 5) + (kk >> 5)]);
    float v0 = c_lut[c.x & 15] * s;
    float v1 = c_lut[c.y & 15] * s;
    float v2 = c_lut[c.z & 15] * s;
    float v3 = c_lut[c.w & 15] * s;
    reinterpret_cast<__half2*>(out)[2 * i + 0] = __floats2half2_rn(v0, v1);
    reinterpret_cast<__half2*>(out)[2 * i + 1] = __floats2half2_rn(v2, v3);
}

// ---------------- GEMM: C[M,N] = A[M,K](fp16) * B[N,K]^T(fp16) + bias ----------------
// R11 resource shape (PROVEN BEST): CTA 128x128x32, 8 warps (2x4), warp tile 64x32,
// 3-stage ring, 80B pitch, regs<=128 -> 2 CTAs/SM.
// CHANGES vs R11 (scheduling only):
//   1) prefetch issued right after barrier (overlaps THIS iter's compute, 2x DMA slack)
//   2) all 4 B-ldsm hoisted to iter top; per-mi A-ldsm km0+km1 pair -> 8 MMAs
//      (each LDSM amortized over 8 dependent MMAs instead of 4)
#define TILE_B  (128 * 80)            // 10240 B per matrix tile (128 rows x 32 halves)
#define STAGE_B (2 * TILE_B)          // A + B = 20480 B
#define NSTAGE  3
#define SMEM_SZ (NSTAGE * STAGE_B)    // 61440 B

template <bool STORE_HALF>
__global__ void __launch_bounds__(256)
gemm_kernel(const __half* __restrict__ A,
            const __half* __restrict__ B,
            const float* __restrict__ bias,
            float* __restrict__ Cf,
            __half* __restrict__ Ch,
            int M, int N, int K) {
    extern __shared__ char smem[];
    const int tid  = threadIdx.x;
    const int lane = tid & 31;
    const int warp = tid >> 5;
    const int wm = warp >> 2;     // 0..1 -> 64-row half
    const int wn = warp & 3;      // 0..3 -> 32-col slice
    const int m0 = blockIdx.y * 128;
    const int n0 = blockIdx.x * 128;

    const __half* gA = A + (size_t)m0 * K;
    const __half* gB = B + (size_t)n0 * K;

    float acc[4][4][4];
#pragma unroll
    for (int a = 0; a < 4; a++)
#pragma unroll
        for (int b = 0; b < 4; b++)
#pragma unroll
            for (int r = 0; r < 4; r++) acc[a][b][r] = 0.f;

    // fill addressing: per matrix 512 16B-chunks (128 rows x 4), 256 threads -> 2 iters
    const int fr0 = tid >> 2,           fc = tid & 3;   // rows 0..63
    const int fr1 = (tid + 256) >> 2;                   // rows 64..127

    // ldmatrix lane addressing
    const int a_row = lane & 15;
    const int a_kc  = lane >> 4;                        // 0/1 -> +8 halves
    const int b_mat = lane >> 3;
    const int b_nr  = ((b_mat >> 1) << 3) + (lane & 7);
    const int b_kc  = b_mat & 1;

    const int KT = K >> 5;  // 128 k-iters of 32

    auto prefetch = [&](int slot, int k0) {
        char* sA = smem + slot * STAGE_B;
        char* sB = sA + TILE_B;
        cp16(sA + fr0 * 80 + fc * 16, gA + (size_t)fr0 * K + k0 + fc * 8);
        cp16(sA + fr1 * 80 + fc * 16, gA + (size_t)fr1 * K + k0 + fc * 8);
        cp16(sB + fr0 * 80 + fc * 16, gB + (size_t)fr0 * K + k0 + fc * 8);
        cp16(sB + fr1 * 80 + fc * 16, gB + (size_t)fr1 * K + k0 + fc * 8);
    };

    // prologue: stages 0,1 in flight
    prefetch(0, 0);  cp_commit();
    prefetch(1, 32); cp_commit();

    int slot = 0, pslot = 2;   // compute slot, prefetch slot
    for (int kt = 0; kt < KT; ++kt) {
        cp_wait1();            // group kt complete (group kt+1 may still fly)
        __syncthreads();       // publish; clears slot-reuse hazard on pslot

        // 1) prefetch FIRST: cp.async flies during this iter's compute too
        if (kt + 2 < KT) prefetch(pslot, (kt + 2) * 32);
        cp_commit();           // uniform group counting

        char* sA = smem + slot * STAGE_B;
        char* sB = sA + TILE_B;

        // 2) all B fragments for both km halves up front
        uint32_t bfr[2][8];
#pragma unroll
        for (int km = 0; km < 2; ++km)
#pragma unroll
            for (int g = 0; g < 2; ++g) {
                int off = (wn * 32 + g * 16 + b_nr) * 80 + (km * 16 + b_kc * 8) * 2;
                ldsm4(bfr[km] + 4 * g, sB + off);
            }

        // per mi: A-ldsm pair (km0,km1) then 8 MMAs
#pragma unroll
        for (int mi = 0; mi < 4; ++mi) {
            uint32_t af[2][4];
            int rowoff = (wm * 64 + mi * 16 + a_row) * 80;
            ldsm4(af[0], sA + rowoff + (a_kc * 8) * 2);
            ldsm4(af[1], sA + rowoff + (16 + a_kc * 8) * 2);
#pragma unroll
            for (int km = 0; km < 2; ++km)
#pragma unroll
                for (int ni = 0; ni < 4; ++ni)
                    mma16816(acc[mi][ni], af[km], &bfr[km][(ni >> 1) * 4 + (ni & 1) * 2]);
        }

        slot  = (slot  == 2) ? 0 : slot + 1;
        pslot = (pslot == 2) ? 0 : pslot + 1;
    }

    // ---- epilogue (registers only; no smem hazard)
    const int r_row = lane >> 2;
    const int r_col = (lane & 3) * 2;
#pragma unroll
    for (int mi = 0; mi < 4; ++mi) {
#pragma unroll
        for (int ni = 0; ni < 4; ++ni) {
            int n = n0 + wn * 32 + ni * 8 + r_col;
            float2 bb = *reinterpret_cast<const float2*>(bias + n);
#pragma unroll
            for (int rr = 0; rr < 2; ++rr) {
                int m = m0 + wm * 64 + mi * 16 + r_row + 8 * rr;
                float v0 = acc[mi][ni][2 * rr + 0] + bb.x;
                float v1 = acc[mi][ni][2 * rr + 1] + bb.y;
                if (STORE_HALF) {
                    *reinterpret_cast<__half2*>(Ch + (size_t)m * N + n) =
                        __floats2half2_rn(v0, v1);
                } else {
                    float2 o; o.x = v0; o.y = v1;
                    *reinterpret_cast<float2*>(Cf + (size_t)m * N + n) = o;
                }
            }
        }
    }
}

// ---------------- launch ----------------
extern "C" void kernel_launch(void* const* d_in, const int* in_sizes, int n_in,
                              void* d_out, int out_size) {
    const float* x   = (const float*)d_in[0];
    const int*   w1c = (const int*)d_in[1];
    const float* w1s = (const float*)d_in[2];
    const float* b1  = (const float*)d_in[3];
    const int*   w2c = (const int*)d_in[4];
    const float* w2s = (const float*)d_in[5];
    const float* b2  = (const float*)d_in[6];
    float* out = (float*)d_out;

    __half *w1h, *w2h, *xh, *hh;
    cudaGetSymbolAddress((void**)&w1h, g_w1);
    cudaGetSymbolAddress((void**)&w2h, g_w2);
    cudaGetSymbolAddress((void**)&xh,  g_x);
    cudaGetSymbolAddress((void**)&hh,  g_h);

    const int thr = 256;
    const int xt4 = T_DIM * D_DIM / 4;
    const int wt4 = D_DIM * D_DIM / 4;

    cvt_kernel<<<(xt4 + thr - 1) / thr, thr>>>(x, xh, xt4);
    dequant_kernel<<<(wt4 + thr - 1) / thr, thr>>>(w1c, w1s, w1h, wt4);
    dequant_kernel<<<(wt4 + thr - 1) / thr, thr>>>(w2c, w2s, w2h, wt4);

    cudaFuncSetAttribute(gemm_kernel<true>,
                         cudaFuncAttributeMaxDynamicSharedMemorySize, SMEM_SZ);
    cudaFuncSetAttribute(gemm_kernel<false>,
                         cudaFuncAttributeMaxDynamicSharedMemorySize, SMEM_SZ);

    dim3 grid(D_DIM / 128, T_DIM / 128);  // n fastest: W (32MB fp16) stays L2-resident
    gemm_kernel<true><<<grid, 256, SMEM_SZ>>>(xh, w1h, b1, nullptr, hh,
                                              T_DIM, D_DIM, D_DIM);
    gemm_kernel<false><<<grid, 256, SMEM_SZ>>>(hh, w2h, b2, out, nullptr,
                                               T_DIM, D_DIM, D_DIM);
}

// round 15
// speedup vs baseline: 1.2050x; 1.2050x over previous
#include <cuda_runtime.h>
#include <cuda_fp16.h>
#include <cstdint>

// ---------------- problem constants ----------------
#define T_DIM 8192
#define D_DIM 4096

// ---------------- scratch (static device globals; no allocation) ----------------
static __device__ __half g_w1[(size_t)D_DIM * D_DIM];
static __device__ __half g_w2[(size_t)D_DIM * D_DIM];
static __device__ __half g_x [(size_t)T_DIM * D_DIM];
static __device__ __half g_h [(size_t)T_DIM * D_DIM];

__constant__ float c_lut[16] = {0.f, 0.5f, 1.f, 1.5f, 2.f, 3.f, 4.f, 6.f,
                                -0.f, -0.5f, -1.f, -1.5f, -2.f, -3.f, -4.f, -6.f};

// ---------------- PTX helpers ----------------
__device__ __forceinline__ void cp16(void* s, const void* g) {
    uint32_t sa = (uint32_t)__cvta_generic_to_shared(s);
    asm volatile("cp.async.cg.shared.global [%0], [%1], 16;\n" :: "r"(sa), "l"(g));
}
__device__ __forceinline__ void cp_commit() { asm volatile("cp.async.commit_group;\n"); }
__device__ __forceinline__ void cp_wait1()  { asm volatile("cp.async.wait_group 1;\n"); }

__device__ __forceinline__ void ldsm4(uint32_t* r, const void* p) {
    uint32_t a = (uint32_t)__cvta_generic_to_shared(p);
    asm volatile("ldmatrix.sync.aligned.m8n8.x4.shared.b16 {%0,%1,%2,%3}, [%4];\n"
                 : "=r"(r[0]), "=r"(r[1]), "=r"(r[2]), "=r"(r[3]) : "r"(a));
}
__device__ __forceinline__ void mma16816(float* c, const uint32_t* a, const uint32_t* b) {
    asm volatile("mma.sync.aligned.m16n8k16.row.col.f32.f16.f16.f32 "
                 "{%0,%1,%2,%3}, {%4,%5,%6,%7}, {%8,%9}, {%0,%1,%2,%3};\n"
                 : "+f"(c[0]), "+f"(c[1]), "+f"(c[2]), "+f"(c[3])
                 : "r"(a[0]), "r"(a[1]), "r"(a[2]), "r"(a[3]), "r"(b[0]), "r"(b[1]));
}

// ---------------- fused prologue kernel ----------------
// Block ranges:  [0, XB)          : fp32 x -> fp16
//                [XB, XB+WB)      : dequant W1 -> fp16
//                [XB+WB, XB+2WB)  : dequant W2 -> fp16
// One launch => all three DRAM streams fill the chip in a single wave train.
#define XT4 (T_DIM * D_DIM / 4)     // 8388608 float4-chunks
#define WT4 (D_DIM * D_DIM / 4)     // 4194304 int4-chunks
#define XB  (XT4 / 256)             // 32768 blocks
#define WB  (WT4 / 256)             // 16384 blocks

__device__ __forceinline__ void dequant_chunk(const int* __restrict__ codes,
                                              const float* __restrict__ scales,
                                              __half* __restrict__ out, int i) {
    int4 c = reinterpret_cast<const int4*>(codes)[i];
    int base = i * 4;
    int row = base >> 12;            // / D_DIM
    int kk  = base & (D_DIM - 1);
    float s = __ldg(&scales[row * (D_DIM >> 5) + (kk >> 5)]);
    float v0 = c_lut[c.x & 15] * s;
    float v1 = c_lut[c.y & 15] * s;
    float v2 = c_lut[c.z & 15] * s;
    float v3 = c_lut[c.w & 15] * s;
    reinterpret_cast<__half2*>(out)[2 * i + 0] = __floats2half2_rn(v0, v1);
    reinterpret_cast<__half2*>(out)[2 * i + 1] = __floats2half2_rn(v2, v3);
}

__global__ void prologue_kernel(const float* __restrict__ x,
                                const int* __restrict__ w1c, const float* __restrict__ w1s,
                                const int* __restrict__ w2c, const float* __restrict__ w2s,
                                __half* __restrict__ xh,
                                __half* __restrict__ w1h,
                                __half* __restrict__ w2h) {
    int b = blockIdx.x;
    if (b < XB) {
        int i = b * 256 + threadIdx.x;
        float4 v = reinterpret_cast<const float4*>(x)[i];
        reinterpret_cast<__half2*>(xh)[2 * i + 0] = __floats2half2_rn(v.x, v.y);
        reinterpret_cast<__half2*>(xh)[2 * i + 1] = __floats2half2_rn(v.z, v.w);
    } else if (b < XB + WB) {
        int i = (b - XB) * 256 + threadIdx.x;
        dequant_chunk(w1c, w1s, w1h, i);
    } else {
        int i = (b - XB - WB) * 256 + threadIdx.x;
        dequant_chunk(w2c, w2s, w2h, i);
    }
}

// ---------------- GEMM: C[M,N] = A[M,K](fp16) * B[N,K]^T(fp16) + bias ----------------
// BYTE-IDENTICAL to R11 (proven best: 741us/GEMM, tensor 61%, regs 121, 2 CTAs/SM).
// CTA tile 128x128x32, 8 warps (2x4), warp tile 64x32, 3-stage cp.async ring,
// 80B pitch (8 rows at stride 80B cover all 32 banks -> LDSM conflict-free).
#define TILE_B  (128 * 80)            // 10240 B per matrix tile (128 rows x 32 halves)
#define STAGE_B (2 * TILE_B)          // A + B = 20480 B
#define NSTAGE  3
#define SMEM_SZ (NSTAGE * STAGE_B)    // 61440 B

template <bool STORE_HALF>
__global__ void __launch_bounds__(256)
gemm_kernel(const __half* __restrict__ A,
            const __half* __restrict__ B,
            const float* __restrict__ bias,
            float* __restrict__ Cf,
            __half* __restrict__ Ch,
            int M, int N, int K) {
    extern __shared__ char smem[];
    const int tid  = threadIdx.x;
    const int lane = tid & 31;
    const int warp = tid >> 5;
    const int wm = warp >> 2;     // 0..1 -> 64-row half
    const int wn = warp & 3;      // 0..3 -> 32-col slice
    const int m0 = blockIdx.y * 128;
    const int n0 = blockIdx.x * 128;

    const __half* gA = A + (size_t)m0 * K;
    const __half* gB = B + (size_t)n0 * K;

    float acc[4][4][4];
#pragma unroll
    for (int a = 0; a < 4; a++)
#pragma unroll
        for (int b = 0; b < 4; b++)
#pragma unroll
            for (int r = 0; r < 4; r++) acc[a][b][r] = 0.f;

    // fill addressing: per matrix 512 16B-chunks (128 rows x 4), 256 threads -> 2 iters
    const int fr0 = tid >> 2,           fc = tid & 3;   // rows 0..63
    const int fr1 = (tid + 256) >> 2;                   // rows 64..127

    // ldmatrix lane addressing
    const int a_row = lane & 15;
    const int a_kc  = lane >> 4;                        // 0/1 -> +8 halves
    const int b_mat = lane >> 3;
    const int b_nr  = ((b_mat >> 1) << 3) + (lane & 7);
    const int b_kc  = b_mat & 1;

    const int KT = K >> 5;  // 128 k-iters of 32

    auto prefetch = [&](int slot, int k0) {
        char* sA = smem + slot * STAGE_B;
        char* sB = sA + TILE_B;
        cp16(sA + fr0 * 80 + fc * 16, gA + (size_t)fr0 * K + k0 + fc * 8);
        cp16(sA + fr1 * 80 + fc * 16, gA + (size_t)fr1 * K + k0 + fc * 8);
        cp16(sB + fr0 * 80 + fc * 16, gB + (size_t)fr0 * K + k0 + fc * 8);
        cp16(sB + fr1 * 80 + fc * 16, gB + (size_t)fr1 * K + k0 + fc * 8);
    };

    // prologue: stages 0,1 in flight
    prefetch(0, 0);  cp_commit();
    prefetch(1, 32); cp_commit();

    int slot = 0, pslot = 2;   // compute slot, prefetch slot (avoid % by 3)
    for (int kt = 0; kt < KT; ++kt) {
        cp_wait1();            // group kt complete (group kt+1 may still fly)
        __syncthreads();       // publish to all warps; clears slot-reuse hazard

        char* sA = smem + slot * STAGE_B;
        char* sB = sA + TILE_B;
#pragma unroll
        for (int km = 0; km < 2; ++km) {
            uint32_t bfr[8];
#pragma unroll
            for (int g = 0; g < 2; ++g) {
                int off = (wn * 32 + g * 16 + b_nr) * 80 + (km * 16 + b_kc * 8) * 2;
                ldsm4(bfr + 4 * g, sB + off);
            }
#pragma unroll
            for (int mi = 0; mi < 4; ++mi) {
                uint32_t af[4];
                ldsm4(af, sA + (wm * 64 + mi * 16 + a_row) * 80 + (km * 16 + a_kc * 8) * 2);
#pragma unroll
                for (int ni = 0; ni < 4; ++ni)
                    mma16816(acc[mi][ni], af, &bfr[(ni >> 1) * 4 + (ni & 1) * 2]);
            }
        }

        // refill slot (kt-1)%3: all readers cleared by the barrier above
        if (kt + 2 < KT) prefetch(pslot, (kt + 2) * 32);
        cp_commit();           // commit every iter (uniform group counting)

        slot  = (slot  == 2) ? 0 : slot + 1;
        pslot = (pslot == 2) ? 0 : pslot + 1;
    }

    // ---- epilogue (registers only; no smem hazard)
    const int r_row = lane >> 2;
    const int r_col = (lane & 3) * 2;
#pragma unroll
    for (int mi = 0; mi < 4; ++mi) {
#pragma unroll
        for (int ni = 0; ni < 4; ++ni) {
            int n = n0 + wn * 32 + ni * 8 + r_col;
            float2 bb = *reinterpret_cast<const float2*>(bias + n);
#pragma unroll
            for (int rr = 0; rr < 2; ++rr) {
                int m = m0 + wm * 64 + mi * 16 + r_row + 8 * rr;
                float v0 = acc[mi][ni][2 * rr + 0] + bb.x;
                float v1 = acc[mi][ni][2 * rr + 1] + bb.y;
                if (STORE_HALF) {
                    *reinterpret_cast<__half2*>(Ch + (size_t)m * N + n) =
                        __floats2half2_rn(v0, v1);
                } else {
                    float2 o; o.x = v0; o.y = v1;
                    *reinterpret_cast<float2*>(Cf + (size_t)m * N + n) = o;
                }
            }
        }
    }
}

// ---------------- launch ----------------
extern "C" void kernel_launch(void* const* d_in, const int* in_sizes, int n_in,
                              void* d_out, int out_size) {
    const float* x   = (const float*)d_in[0];
    const int*   w1c = (const int*)d_in[1];
    const float* w1s = (const float*)d_in[2];
    const float* b1  = (const float*)d_in[3];
    const int*   w2c = (const int*)d_in[4];
    const float* w2s = (const float*)d_in[5];
    const float* b2  = (const float*)d_in[6];
    float* out = (float*)d_out;

    __half *w1h, *w2h, *xh, *hh;
    cudaGetSymbolAddress((void**)&w1h, g_w1);
    cudaGetSymbolAddress((void**)&w2h, g_w2);
    cudaGetSymbolAddress((void**)&xh,  g_x);
    cudaGetSymbolAddress((void**)&hh,  g_h);

    // single fused prologue launch: cvt + dequant W1 + dequant W2
    prologue_kernel<<<XB + 2 * WB, 256>>>(x, w1c, w1s, w2c, w2s, xh, w1h, w2h);

    cudaFuncSetAttribute(gemm_kernel<true>,
                         cudaFuncAttributeMaxDynamicSharedMemorySize, SMEM_SZ);
    cudaFuncSetAttribute(gemm_kernel<false>,
                         cudaFuncAttributeMaxDynamicSharedMemorySize, SMEM_SZ);

    dim3 grid(D_DIM / 128, T_DIM / 128);  // n fastest: W (32MB fp16) stays L2-resident
    gemm_kernel<true><<<grid, 256, SMEM_SZ>>>(xh, w1h, b1, nullptr, hh,
                                              T_DIM, D_DIM, D_DIM);
    gemm_kernel<false><<<grid, 256, SMEM_SZ>>>(hh, w2h, b2, out, nullptr,
                                               T_DIM, D_DIM, D_DIM);
}